// round 16
// baseline (speedup 1.0000x reference)
#include <cuda_runtime.h>
#include <cuda_bf16.h>
#include <math_constants.h>

#define B 4
#define NPTS 1024
#define KNB 80

// ---------------- scratch (device globals) ----------------
__device__ float g_G[(size_t)B * NPTS * NPTS];    // neg_dist matrices
__device__ int   g_idx[B * NPTS * KNB];
__device__ float g_u[(size_t)B * NPTS * 128];
__device__ float g_v[(size_t)B * NPTS * 128];
__device__ double g_gs[48];
__device__ unsigned int g_ymax[B * 1024];
__device__ unsigned int g_ymin[B * 1024];
__device__ double g_gs5[64];
__device__ unsigned int g_cnt;
__device__ unsigned int g_flag;

__device__ __forceinline__ unsigned int fenc(float f) {
    unsigned int b = __float_as_uint(f);
    return (b & 0x80000000u) ? ~b : (b | 0x80000000u);
}
__device__ __forceinline__ float fdec(unsigned int u) {
    unsigned int b = (u & 0x80000000u) ? (u & 0x7FFFFFFFu) : ~u;
    return __uint_as_float(b);
}

// software grid barrier (256 co-resident blocks; epoch monotone per replay)
__device__ __forceinline__ void grid_barrier(unsigned int epoch, unsigned int nb) {
    __threadfence();
    __syncthreads();
    if (threadIdx.x == 0) {
        unsigned int a = atomicAdd(&g_cnt, 1u);
        if (a == nb - 1u) { g_cnt = 0u; __threadfence(); atomicExch(&g_flag, epoch); }
        while (atomicAdd(&g_flag, 0u) < epoch) __nanosleep(64);
    }
    __syncthreads();
}

// ---------------- zero/re-arm kernel (proven 3us) ----------------
__global__ void zero_all_kernel() {
    int i = blockIdx.x * 256 + threadIdx.x;
    if (i < B * 1024) { g_ymax[i] = 0u; g_ymin[i] = 0xFFFFFFFFu; }
    if (i < 48) g_gs[i] = 0.0;
    if (i < 64) g_gs5[i] = 0.0;
    if (i == 0) { g_cnt = 0u; g_flag = 0u; }
}

// ---------------- gram C=3 (proven ~10us; static smem) ----------------
__global__ __launch_bounds__(256, 2) void gram3_kernel(const float* __restrict__ x, int bstride) {
    int b = blockIdx.z;
    int n0 = blockIdx.y * 128, m0 = blockIdx.x * 128;
    __shared__ float As[3][132];
    __shared__ float Bs[3][132];
    int t = threadIdx.x;
    int tx = t & 15, ty = t >> 4;
    float acc[8][8] = {};
    float sa[8] = {}, sb[8] = {};
    const float* xb = x + (size_t)b * bstride;
    for (int i = t; i < 3 * 128; i += 256) {
        int c = i >> 7, l = i & 127;
        As[c][l] = xb[(size_t)c * NPTS + n0 + l];
        Bs[c][l] = xb[(size_t)c * NPTS + m0 + l];
    }
    __syncthreads();
#pragma unroll
    for (int c = 0; c < 3; c++) {
        float a[8], bb[8];
        const float4* a4 = (const float4*)&As[c][ty * 8];
        const float4* b4 = (const float4*)&Bs[c][tx * 8];
        float4 av0 = a4[0], av1 = a4[1];
        float4 bv0 = b4[0], bv1 = b4[1];
        a[0]=av0.x;a[1]=av0.y;a[2]=av0.z;a[3]=av0.w;a[4]=av1.x;a[5]=av1.y;a[6]=av1.z;a[7]=av1.w;
        bb[0]=bv0.x;bb[1]=bv0.y;bb[2]=bv0.z;bb[3]=bv0.w;bb[4]=bv1.x;bb[5]=bv1.y;bb[6]=bv1.z;bb[7]=bv1.w;
#pragma unroll
        for (int i = 0; i < 8; i++) sa[i] = fmaf(a[i], a[i], sa[i]);
#pragma unroll
        for (int j = 0; j < 8; j++) sb[j] = fmaf(bb[j], bb[j], sb[j]);
#pragma unroll
        for (int i = 0; i < 8; i++)
#pragma unroll
            for (int j = 0; j < 8; j++) acc[i][j] = fmaf(a[i], bb[j], acc[i][j]);
    }
    float* Gb = g_G + ((size_t)b << 20);
#pragma unroll
    for (int i = 0; i < 8; i++) {
        float* row = Gb + (size_t)(n0 + ty * 8 + i) * NPTS + m0 + tx * 8;
        float4 v0, v1;
        v0.x = 2.f*acc[i][0]-sa[i]-sb[0]; v0.y = 2.f*acc[i][1]-sa[i]-sb[1];
        v0.z = 2.f*acc[i][2]-sa[i]-sb[2]; v0.w = 2.f*acc[i][3]-sa[i]-sb[3];
        v1.x = 2.f*acc[i][4]-sa[i]-sb[4]; v1.y = 2.f*acc[i][5]-sa[i]-sb[5];
        v1.z = 2.f*acc[i][6]-sa[i]-sb[6]; v1.w = 2.f*acc[i][7]-sa[i]-sb[7];
        *(float4*)row = v0;
        *(float4*)(row + 4) = v1;
    }
}

// ---------------- gram C=64 v2: full-K tile in dynamic smem, ONE sync ----------------
#define GRAM64_SMEM (2 * 64 * 132 * 4)   // 67,584 B -> 2 CTAs/SM
__global__ __launch_bounds__(256, 2) void gram64_kernel(const float* __restrict__ x, int bstride) {
    extern __shared__ float sg64[];
    float (*As)[132] = (float(*)[132])sg64;
    float (*Bs)[132] = (float(*)[132])(sg64 + 64 * 132);
    int b = blockIdx.z;
    int n0 = blockIdx.y * 128, m0 = blockIdx.x * 128;
    int t = threadIdx.x;
    int tx = t & 15, ty = t >> 4;
    float acc[8][8] = {};
    float sa[8] = {}, sb[8] = {};
    const float* xb = x + (size_t)b * bstride;
#pragma unroll 8
    for (int i = t; i < 64 * 128; i += 256) {
        int c = i >> 7, l = i & 127;
        As[c][l] = xb[(size_t)c * NPTS + n0 + l];
        Bs[c][l] = xb[(size_t)c * NPTS + m0 + l];
    }
    __syncthreads();
#pragma unroll
    for (int c = 0; c < 64; c++) {
        float a[8], bb[8];
        const float4* a4 = (const float4*)&As[c][ty * 8];
        const float4* b4 = (const float4*)&Bs[c][tx * 8];
        float4 av0 = a4[0], av1 = a4[1];
        float4 bv0 = b4[0], bv1 = b4[1];
        a[0]=av0.x;a[1]=av0.y;a[2]=av0.z;a[3]=av0.w;a[4]=av1.x;a[5]=av1.y;a[6]=av1.z;a[7]=av1.w;
        bb[0]=bv0.x;bb[1]=bv0.y;bb[2]=bv0.z;bb[3]=bv0.w;bb[4]=bv1.x;bb[5]=bv1.y;bb[6]=bv1.z;bb[7]=bv1.w;
#pragma unroll
        for (int i = 0; i < 8; i++) sa[i] = fmaf(a[i], a[i], sa[i]);
#pragma unroll
        for (int j = 0; j < 8; j++) sb[j] = fmaf(bb[j], bb[j], sb[j]);
#pragma unroll
        for (int i = 0; i < 8; i++)
#pragma unroll
            for (int j = 0; j < 8; j++) acc[i][j] = fmaf(a[i], bb[j], acc[i][j]);
    }
    float* Gb = g_G + ((size_t)b << 20);
#pragma unroll
    for (int i = 0; i < 8; i++) {
        float* row = Gb + (size_t)(n0 + ty * 8 + i) * NPTS + m0 + tx * 8;
        float4 v0, v1;
        v0.x = 2.f*acc[i][0]-sa[i]-sb[0]; v0.y = 2.f*acc[i][1]-sa[i]-sb[1];
        v0.z = 2.f*acc[i][2]-sa[i]-sb[2]; v0.w = 2.f*acc[i][3]-sa[i]-sb[3];
        v1.x = 2.f*acc[i][4]-sa[i]-sb[4]; v1.y = 2.f*acc[i][5]-sa[i]-sb[5];
        v1.z = 2.f*acc[i][6]-sa[i]-sb[6]; v1.w = 2.f*acc[i][7]-sa[i]-sb[7];
        *(float4*)row = v0;
        *(float4*)(row + 4) = v1;
    }
}

// ---------------- knn: top-80 per row, 4-pass radix select (proven, 30us) ----------------
__global__ __launch_bounds__(256) void knn_kernel() {
    int bn = blockIdx.x;
    int b = bn >> 10;
    __shared__ unsigned int skeys[NPTS];
    __shared__ int hist[256];
    __shared__ int wtot[8];
    __shared__ int s_bsel, s_above, s_cnt, s_ecnt;
    __shared__ int s_eq[128];
    const float4* nd4 = (const float4*)(g_G + ((size_t)b << 20) + ((size_t)(bn & 1023) << 10));
    int t = threadIdx.x;
    int lane = t & 31, w = t >> 5;
    float4 d = nd4[t];
    unsigned int rkeys[4] = { fenc(d.x), fenc(d.y), fenc(d.z), fenc(d.w) };
    ((uint4*)skeys)[t] = make_uint4(rkeys[0], rkeys[1], rkeys[2], rkeys[3]);
    unsigned int prefix = 0, pmask = 0;
    int need = KNB;
    for (int shift = 24; shift >= 0; shift -= 8) {
        hist[t] = 0;
        __syncthreads();
#pragma unroll
        for (int j = 0; j < 4; j++) {
            unsigned int k = rkeys[j];
            bool act = ((k & pmask) == prefix);
            int bin = act ? (int)((k >> shift) & 255) : (300 + j);
            unsigned int m = __match_any_sync(0xffffffffu, bin);
            if (act && ((m & ((1u << lane) - 1u)) == 0u))
                atomicAdd(&hist[bin], __popc(m));
        }
        __syncthreads();
        int c = hist[t];
        int s = c;
#pragma unroll
        for (int off = 1; off < 32; off <<= 1) {
            int o = __shfl_down_sync(0xffffffffu, s, off);
            if (lane + off < 32) s += o;
        }
        if (lane == 0) wtot[w] = s;
        __syncthreads();
        int offsum = 0;
        for (int w2 = w + 1; w2 < 8; w2++) offsum += wtot[w2];
        int sfx = s + offsum;
        int nxt = sfx - c;
        if (sfx >= need && nxt < need) { s_bsel = t; s_above = nxt; }
        __syncthreads();
        prefix |= ((unsigned int)s_bsel) << shift;
        pmask  |= 255u << shift;
        need   -= s_above;
        __syncthreads();
    }
    if (t == 0) { s_cnt = 0; s_ecnt = 0; }
    __syncthreads();
    int* out = g_idx + bn * KNB;
#pragma unroll
    for (int j = 0; j < 4; j++) {
        unsigned int k = rkeys[j];
        int idx = 4 * t + j;
        bool gt = (k > prefix);
        unsigned int bal = __ballot_sync(0xffffffffu, gt);
        if (bal) {
            int ldr = __ffs(bal) - 1;
            int base = 0;
            if (lane == ldr) base = atomicAdd(&s_cnt, __popc(bal));
            base = __shfl_sync(0xffffffffu, base, ldr);
            if (gt) out[base + __popc(bal & ((1u << lane) - 1u))] = idx;
        }
        bool eq = (k == prefix);
        unsigned int be = __ballot_sync(0xffffffffu, eq);
        if (be) {
            int ldr = __ffs(be) - 1;
            int base = 0;
            if (lane == ldr) base = atomicAdd(&s_ecnt, __popc(be));
            base = __shfl_sync(0xffffffffu, base, ldr);
            if (eq) {
                int p = base + __popc(be & ((1u << lane) - 1u));
                if (p < 128) s_eq[p] = idx;
            }
        }
    }
    __syncthreads();
    if (t == 0) {
        int p = s_cnt;
        int L = s_ecnt;
        if (L == need && L <= 128) {
            for (int i = 0; i < L; i++) out[p++] = s_eq[i];
        } else if (L <= 128) {
            for (int r = 0; r < need; r++) {
                int bi = -1, bv = 0x7FFFFFFF;
                for (int i = 0; i < L; i++) {
                    int v = s_eq[i];
                    if (v >= 0 && v < bv) { bv = v; bi = i; }
                }
                out[p++] = bv;
                s_eq[bi] = -1;
            }
        } else {
            for (int i = 0; i < NPTS && p < KNB; i++)
                if (skeys[i] == prefix) out[p++] = i;
        }
    }
}

// ---------------- uv2: W transposed in smem (proven) ----------------
template<int C, int COUT>
__global__ __launch_bounds__(256) void uv2_kernel(const float* __restrict__ x, int bstride,
                                                  const float* __restrict__ W) {
    extern __shared__ float sm[];
    float* sW = sm;                    // [2C][COUT]
    float* sx = sm + 2 * C * COUT;     // [16][C]
    int t = threadIdx.x;
    int bn0 = blockIdx.x * 16;
    int b = bn0 >> 10, n0 = bn0 & 1023;
    const float* xb = x + (size_t)b * bstride;
    for (int i = t; i < 2 * C * COUT; i += 256) {
        int o = i % COUT, c = i / COUT;
        sW[i] = W[(size_t)o * 2 * C + c];
    }
    for (int i = t; i < 16 * C; i += 256) {
        int r = i & 15, c = i >> 4;
        sx[r * C + c] = xb[(size_t)c * NPTS + n0 + r];
    }
    __syncthreads();
    for (int i = t; i < 16 * COUT; i += 256) {
        int nl = i / COUT, o = i % COUT;
        float u = 0.f, v = 0.f;
#pragma unroll
        for (int c = 0; c < C; c++) {
            float xv = sx[nl * C + c];
            float w1 = sW[c * COUT + o];
            float w2 = sW[(C + c) * COUT + o];
            u = fmaf(w1, xv, u);
            v = fmaf(w2 - w1, xv, v);
        }
        size_t bn = (size_t)(bn0 + nl);
        g_u[bn * COUT + o] = u;
        g_v[bn * COUT + o] = v;
    }
}

// =====================================================================================
// back_kernel: gather (unroll 8) + stats + grid barrier + GN + leaky + write feat
// =====================================================================================
__global__ __launch_bounds__(256) void back_kernel(int Cout, int gsoff, unsigned int epoch,
                                                   const float* __restrict__ gnw,
                                                   const float* __restrict__ gnb,
                                                   float* __restrict__ feat, int choff) {
    __shared__ int sidx[16 * KNB];
    __shared__ double sacc[4];
    __shared__ double sg[4];
    int t = threadIdx.x, lane = t & 31;
    int TPP = Cout >> 2;
    int ppb = 256 / TPP;
    int passes = 16 / ppb;
    int bn0 = blockIdx.x * 16;
    int b = bn0 >> 10;
    int o4 = t % TPP;
    int pl0 = t / TPP;

    if (t < 4) sacc[t] = 0.0;
    for (int i = t; i < 16 * KNB; i += 256) sidx[i] = g_idx[bn0 * KNB + i];
    __syncthreads();

    const float4* ub = (const float4*)g_u + (size_t)(b << 10) * TPP;
    int half = TPP >> 1;
    int g = o4 / half;
    float4 rymx[2], rymn[2];
    const float Kf = (float)KNB;

    for (int p = 0; p < passes; p++) {
        int pl = p * ppb + pl0;
        int bn = bn0 + pl;
        const int* myidx = sidx + pl * KNB;
        float4 mx = make_float4(-CUDART_INF_F, -CUDART_INF_F, -CUDART_INF_F, -CUDART_INF_F);
        float4 mn = make_float4(CUDART_INF_F, CUDART_INF_F, CUDART_INF_F, CUDART_INF_F);
        float4 s1 = make_float4(0, 0, 0, 0), s2 = make_float4(0, 0, 0, 0);
        for (int k = 0; k < KNB; k += 8) {
            float4 v0 = ub[(size_t)myidx[k] * TPP + o4];
            float4 v1 = ub[(size_t)myidx[k + 1] * TPP + o4];
            float4 v2 = ub[(size_t)myidx[k + 2] * TPP + o4];
            float4 v3 = ub[(size_t)myidx[k + 3] * TPP + o4];
            float4 v4 = ub[(size_t)myidx[k + 4] * TPP + o4];
            float4 v5 = ub[(size_t)myidx[k + 5] * TPP + o4];
            float4 v6 = ub[(size_t)myidx[k + 6] * TPP + o4];
            float4 v7 = ub[(size_t)myidx[k + 7] * TPP + o4];
#define ACC(vv) \
            mx.x = fmaxf(mx.x, vv.x); mn.x = fminf(mn.x, vv.x); s1.x += vv.x; s2.x = fmaf(vv.x, vv.x, s2.x); \
            mx.y = fmaxf(mx.y, vv.y); mn.y = fminf(mn.y, vv.y); s1.y += vv.y; s2.y = fmaf(vv.y, vv.y, s2.y); \
            mx.z = fmaxf(mx.z, vv.z); mn.z = fminf(mn.z, vv.z); s1.z += vv.z; s2.z = fmaf(vv.z, vv.z, s2.z); \
            mx.w = fmaxf(mx.w, vv.w); mn.w = fminf(mn.w, vv.w); s1.w += vv.w; s2.w = fmaf(vv.w, vv.w, s2.w);
            ACC(v0) ACC(v1) ACC(v2) ACC(v3) ACC(v4) ACC(v5) ACC(v6) ACC(v7)
#undef ACC
        }
        float4 v = ((const float4*)g_v)[(size_t)bn * TPP + o4];
        rymx[p] = make_float4(mx.x + v.x, mx.y + v.y, mx.z + v.z, mx.w + v.w);
        rymn[p] = make_float4(mn.x + v.x, mn.y + v.y, mn.z + v.z, mn.w + v.w);
        float S1 = (s1.x + Kf * v.x) + (s1.y + Kf * v.y) + (s1.z + Kf * v.z) + (s1.w + Kf * v.w);
        float S2 = (s2.x + 2.f * v.x * s1.x + Kf * v.x * v.x)
                 + (s2.y + 2.f * v.y * s1.y + Kf * v.y * v.y)
                 + (s2.z + 2.f * v.z * s1.z + Kf * v.z * v.z)
                 + (s2.w + 2.f * v.w * s1.w + Kf * v.w * v.w);
#pragma unroll
        for (int off = 8; off > 0; off >>= 1) {
            if (off < half) {
                S1 += __shfl_down_sync(0xffffffffu, S1, off, half);
                S2 += __shfl_down_sync(0xffffffffu, S2, off, half);
            }
        }
        if ((lane & (half - 1)) == 0) {
            int gg = (lane / half) & 1;
            atomicAdd(&sacc[gg * 2 + 0], (double)S1);
            atomicAdd(&sacc[gg * 2 + 1], (double)S2);
        }
    }
    __syncthreads();
    if (t < 4) atomicAdd(&g_gs[gsoff + (b * 2 + (t >> 1)) * 2 + (t & 1)], sacc[t]);

    grid_barrier(epoch, 256u);

    if (t < 4) sg[t] = __ldcg(&g_gs[gsoff + (b * 2 + (t >> 1)) * 2 + (t & 1)]);
    __syncthreads();

    double cntr = (double)(Cout >> 1) * (double)NPTS * (double)KNB;
    double S1g = sg[g * 2 + 0];
    double S2g = sg[g * 2 + 1];
    double mud = S1g / cntr;
    float var = (float)(S2g / cntr - mud * mud);
    float rsq = rsqrtf(var + 1e-5f);
    float mu = (float)mud;
    float A[4], Bb[4];
#pragma unroll
    for (int j = 0; j < 4; j++) {
        int o = 4 * o4 + j;
        A[j] = gnw[o] * rsq;
        Bb[j] = gnb[o] - mu * A[j];
    }
    for (int p = 0; p < passes; p++) {
        int pl = p * ppb + pl0;
        int n = (bn0 & 1023) + pl;
        float* fb = feat + (size_t)b * 262144 + (size_t)choff * NPTS + n;
        float mxv[4] = { rymx[p].x, rymx[p].y, rymx[p].z, rymx[p].w };
        float mnv[4] = { rymn[p].x, rymn[p].y, rymn[p].z, rymn[p].w };
#pragma unroll
        for (int j = 0; j < 4; j++) {
            float c1 = fmaf(A[j], mxv[j], Bb[j]);
            float c2 = fmaf(A[j], mnv[j], Bb[j]);
            c1 = c1 >= 0.f ? c1 : 0.2f * c1;
            c2 = c2 >= 0.f ? c2 : 0.2f * c2;
            fb[(size_t)(4 * o4 + j) * NPTS] = fmaxf(c1, c2);
        }
    }
}

// =====================================================================================
// tail_kernel (proven): final matmul + stats + grid barrier + GN/relu/max output
// =====================================================================================
__global__ __launch_bounds__(256, 2) void tail_kernel(const float* __restrict__ feat,
                                                      const float* __restrict__ W,
                                                      const float* __restrict__ bias,
                                                      const float* __restrict__ gnw,
                                                      const float* __restrict__ gnb,
                                                      float* __restrict__ out) {
    int b = blockIdx.z;
    int co0 = blockIdx.x * 128, n0 = blockIdx.y * 128;
    __shared__ float Ws[32][132];
    __shared__ float Xs[32][128];
    int t = threadIdx.x, tx = t & 15, ty = t >> 4;
    int lane = t & 31, w = t >> 5;
    float acc[8][8] = {};
    const float* fb = feat + (size_t)b * 262144;
#pragma unroll
    for (int cc = 0; cc < 256; cc += 32) {
        __syncthreads();
#pragma unroll 4
        for (int i = t; i < 32 * 128; i += 256) {
            int row = i >> 5, c = i & 31;
            Ws[c][row] = W[(size_t)(co0 + row) * 256 + cc + c];
        }
#pragma unroll 4
        for (int i = t; i < 32 * 128; i += 256) {
            int nl = i & 127, c = i >> 7;
            Xs[c][nl] = fb[(size_t)(cc + c) * NPTS + n0 + nl];
        }
        __syncthreads();
#pragma unroll
        for (int c = 0; c < 32; c++) {
            float wv[8], xv[8];
            const float4* w4 = (const float4*)&Ws[c][ty * 8];
            const float4* x4 = (const float4*)&Xs[c][tx * 8];
            float4 p0 = w4[0], p1 = w4[1], q0 = x4[0], q1 = x4[1];
            wv[0]=p0.x;wv[1]=p0.y;wv[2]=p0.z;wv[3]=p0.w;wv[4]=p1.x;wv[5]=p1.y;wv[6]=p1.z;wv[7]=p1.w;
            xv[0]=q0.x;xv[1]=q0.y;xv[2]=q0.z;xv[3]=q0.w;xv[4]=q1.x;xv[5]=q1.y;xv[6]=q1.z;xv[7]=q1.w;
#pragma unroll
            for (int i = 0; i < 8; i++)
#pragma unroll
                for (int j = 0; j < 8; j++) acc[i][j] = fmaf(wv[i], xv[j], acc[i][j]);
        }
    }
    float s1t = 0.f, s2t = 0.f;
#pragma unroll
    for (int i = 0; i < 8; i++) {
        int co = co0 + ty * 8 + i;
        float bv = bias[co];
        float mx = -CUDART_INF_F, mn = CUDART_INF_F;
#pragma unroll
        for (int j = 0; j < 8; j++) {
            float y = acc[i][j] + bv;
            mx = fmaxf(mx, y); mn = fminf(mn, y);
            s1t += y; s2t = fmaf(y, y, s2t);
        }
#pragma unroll
        for (int off = 8; off > 0; off >>= 1) {
            mx = fmaxf(mx, __shfl_down_sync(0xffffffffu, mx, off, 16));
            mn = fminf(mn, __shfl_down_sync(0xffffffffu, mn, off, 16));
        }
        if (tx == 0) {
            atomicMax(&g_ymax[b * 1024 + co], fenc(mx));
            atomicMin(&g_ymin[b * 1024 + co], fenc(mn));
        }
    }
#pragma unroll
    for (int off = 16; off > 0; off >>= 1) {
        s1t += __shfl_down_sync(0xffffffffu, s1t, off);
        s2t += __shfl_down_sync(0xffffffffu, s2t, off);
    }
    __shared__ double sred[8][2];
    if (lane == 0) { sred[w][0] = (double)s1t; sred[w][1] = (double)s2t; }
    __syncthreads();
    if (t == 0) {
        double a = 0.0, c = 0.0;
        for (int i = 0; i < 8; i++) { a += sred[i][0]; c += sred[i][1]; }
        atomicAdd(&g_gs5[(b * 8 + blockIdx.x) * 2 + 0], a);
        atomicAdd(&g_gs5[(b * 8 + blockIdx.x) * 2 + 1], c);
    }

    grid_barrier(4u, 256u);

    if (t < 16) {
        int bid = blockIdx.x + (blockIdx.y << 3) + ((int)blockIdx.z << 6);
        int i = bid * 16 + t;
        int ob = i >> 10, c = i & 1023;
        int g = c >> 7;
        double cntr = 128.0 * 1024.0;
        double S1 = __ldcg(&g_gs5[(ob * 8 + g) * 2 + 0]);
        double S2 = __ldcg(&g_gs5[(ob * 8 + g) * 2 + 1]);
        double mud = S1 / cntr;
        float var = (float)(S2 / cntr - mud * mud);
        float rsq = rsqrtf(var + 1e-5f);
        float a = gnw[c] * rsq;
        float bb = gnb[c] - (float)mud * a;
        float ymx = fdec(__ldcg(&g_ymax[i]));
        float ymn = fdec(__ldcg(&g_ymin[i]));
        float c1 = fmaxf(fmaf(a, ymx, bb), 0.f);
        float c2 = fmaxf(fmaf(a, ymn, bb), 0.f);
        out[i] = fmaxf(c1, c2);
    }
}

// ---------------- launch ----------------
extern "C" void kernel_launch(void* const* d_in, const int* in_sizes, int n_in,
                              void* d_out, int out_size) {
    const float* x    = (const float*)d_in[0];
    const float* c1w  = (const float*)d_in[1];
    const float* g1w  = (const float*)d_in[2];
    const float* g1b  = (const float*)d_in[3];
    const float* c2w  = (const float*)d_in[4];
    const float* g2w  = (const float*)d_in[5];
    const float* g2b  = (const float*)d_in[6];
    const float* c3w  = (const float*)d_in[7];
    const float* g3w  = (const float*)d_in[8];
    const float* g3b  = (const float*)d_in[9];
    const float* mlpw = (const float*)d_in[10];
    const float* mlpb = (const float*)d_in[11];
    const float* g5w  = (const float*)d_in[12];
    const float* g5b  = (const float*)d_in[13];

    float* out  = (float*)d_out;
    float* feat = out + B * 1024;  // x_features region (B,256,N)

    const int SM_UV3_64   = (2 * 3 * 64 + 16 * 3) * 4;
    const int SM_UV64_64  = (2 * 64 * 64 + 16 * 64) * 4;
    const int SM_UV64_128 = (2 * 64 * 128 + 16 * 64) * 4;
    cudaFuncSetAttribute(uv2_kernel<64, 128>, cudaFuncAttributeMaxDynamicSharedMemorySize, SM_UV64_128);
    cudaFuncSetAttribute(uv2_kernel<64, 64>,  cudaFuncAttributeMaxDynamicSharedMemorySize, SM_UV64_64);
    cudaFuncSetAttribute(gram64_kernel, cudaFuncAttributeMaxDynamicSharedMemorySize, GRAM64_SMEM);

    zero_all_kernel<<<16, 256>>>();                                        // 1
    // layer 1
    uv2_kernel<3, 64><<<256, 256, SM_UV3_64>>>(x, 3 * NPTS, c1w);          // 2
    gram3_kernel<<<dim3(8, 8, B), 256>>>(x, 3 * NPTS);                     // 3
    knn_kernel<<<B * NPTS, 256>>>();                                       // 4 (profiled slot)
    back_kernel<<<256, 256>>>(64, 0, 1u, g1w, g1b, feat, 0);               // 5

    // layer 2
    gram64_kernel<<<dim3(8, 8, B), 256, GRAM64_SMEM>>>(feat, 256 * NPTS);  // 6
    knn_kernel<<<B * NPTS, 256>>>();                                       // 7
    uv2_kernel<64, 64><<<256, 256, SM_UV64_64>>>(feat, 256 * NPTS, c2w);   // 8
    back_kernel<<<256, 256>>>(64, 16, 2u, g2w, g2b, feat, 64);             // 9

    // layer 3
    gram64_kernel<<<dim3(8, 8, B), 256, GRAM64_SMEM>>>(feat + 64 * NPTS, 256 * NPTS); // 10
    knn_kernel<<<B * NPTS, 256>>>();                                       // 11
    uv2_kernel<64, 128><<<256, 256, SM_UV64_128>>>(feat + 64 * NPTS, 256 * NPTS, c3w); // 12
    back_kernel<<<256, 256>>>(128, 32, 3u, g3w, g3b, feat, 128);           // 13

    tail_kernel<<<dim3(8, 8, B), 256>>>(feat, mlpw, mlpb, g5w, g5b, out);  // 14
}

// round 17
// speedup vs baseline: 1.0570x; 1.0570x over previous
#include <cuda_runtime.h>
#include <cuda_bf16.h>
#include <math_constants.h>

#define B 4
#define NPTS 1024
#define KNB 80

// ---------------- scratch (device globals) ----------------
__device__ float g_G[(size_t)B * NPTS * NPTS];    // neg_dist matrices
__device__ int   g_idx[B * NPTS * KNB];
__device__ float g_u[(size_t)B * NPTS * 128];
__device__ float g_v[(size_t)B * NPTS * 128];
__device__ double g_gs[48];
__device__ unsigned int g_ymax[B * 1024];
__device__ unsigned int g_ymin[B * 1024];
__device__ double g_gs5[64];
__device__ unsigned int g_cnt;
__device__ unsigned int g_flag;

__device__ __forceinline__ unsigned int fenc(float f) {
    unsigned int b = __float_as_uint(f);
    return (b & 0x80000000u) ? ~b : (b | 0x80000000u);
}
__device__ __forceinline__ float fdec(unsigned int u) {
    unsigned int b = (u & 0x80000000u) ? (u & 0x7FFFFFFFu) : ~u;
    return __uint_as_float(b);
}

// software grid barrier (256 co-resident blocks; epoch monotone per replay)
__device__ __forceinline__ void grid_barrier(unsigned int epoch, unsigned int nb) {
    __threadfence();
    __syncthreads();
    if (threadIdx.x == 0) {
        unsigned int a = atomicAdd(&g_cnt, 1u);
        if (a == nb - 1u) { g_cnt = 0u; __threadfence(); atomicExch(&g_flag, epoch); }
        while (atomicAdd(&g_flag, 0u) < epoch) __nanosleep(64);
    }
    __syncthreads();
}

// ---------------- zero/re-arm kernel (proven 3us) ----------------
__global__ void zero_all_kernel() {
    int i = blockIdx.x * 256 + threadIdx.x;
    if (i < B * 1024) { g_ymax[i] = 0u; g_ymin[i] = 0xFFFFFFFFu; }
    if (i < 48) g_gs[i] = 0.0;
    if (i < 64) g_gs5[i] = 0.0;
    if (i == 0) { g_cnt = 0u; g_flag = 0u; }
}

// ---------------- gram: templated C, chunked (r13/r15-proven, 25.7us measured) ----------------
template<int C>
__global__ __launch_bounds__(256, 2) void gram_kernel(const float* __restrict__ x, int bstride) {
    int b = blockIdx.z;
    int n0 = blockIdx.y * 128, m0 = blockIdx.x * 128;
    __shared__ float As[32][132];
    __shared__ float Bs[32][132];
    int t = threadIdx.x;
    int tx = t & 15, ty = t >> 4;
    float acc[8][8] = {};
    float sa[8] = {}, sb[8] = {};
    const float* xb = x + (size_t)b * bstride;
#pragma unroll
    for (int cc = 0; cc < C; cc += 32) {
        const int CH = (C - cc < 32) ? (C - cc) : 32;
        __syncthreads();
#pragma unroll 4
        for (int i = t; i < 32 * 128; i += 256) {
            int c = i >> 7, l = i & 127;
            float av = 0.f, bv = 0.f;
            if (c < CH) {
                av = xb[(size_t)(cc + c) * NPTS + n0 + l];
                bv = xb[(size_t)(cc + c) * NPTS + m0 + l];
            }
            As[c][l] = av; Bs[c][l] = bv;
        }
        __syncthreads();
#pragma unroll
        for (int c = 0; c < CH; c++) {
            float a[8], bb[8];
            const float4* a4 = (const float4*)&As[c][ty * 8];
            const float4* b4 = (const float4*)&Bs[c][tx * 8];
            float4 av0 = a4[0], av1 = a4[1];
            float4 bv0 = b4[0], bv1 = b4[1];
            a[0]=av0.x;a[1]=av0.y;a[2]=av0.z;a[3]=av0.w;a[4]=av1.x;a[5]=av1.y;a[6]=av1.z;a[7]=av1.w;
            bb[0]=bv0.x;bb[1]=bv0.y;bb[2]=bv0.z;bb[3]=bv0.w;bb[4]=bv1.x;bb[5]=bv1.y;bb[6]=bv1.z;bb[7]=bv1.w;
#pragma unroll
            for (int i = 0; i < 8; i++) sa[i] = fmaf(a[i], a[i], sa[i]);
#pragma unroll
            for (int j = 0; j < 8; j++) sb[j] = fmaf(bb[j], bb[j], sb[j]);
#pragma unroll
            for (int i = 0; i < 8; i++)
#pragma unroll
                for (int j = 0; j < 8; j++) acc[i][j] = fmaf(a[i], bb[j], acc[i][j]);
        }
    }
    float* Gb = g_G + ((size_t)b << 20);
#pragma unroll
    for (int i = 0; i < 8; i++) {
        float* row = Gb + (size_t)(n0 + ty * 8 + i) * NPTS + m0 + tx * 8;
        float4 v0, v1;
        v0.x = 2.f*acc[i][0]-sa[i]-sb[0]; v0.y = 2.f*acc[i][1]-sa[i]-sb[1];
        v0.z = 2.f*acc[i][2]-sa[i]-sb[2]; v0.w = 2.f*acc[i][3]-sa[i]-sb[3];
        v1.x = 2.f*acc[i][4]-sa[i]-sb[4]; v1.y = 2.f*acc[i][5]-sa[i]-sb[5];
        v1.z = 2.f*acc[i][6]-sa[i]-sb[6]; v1.w = 2.f*acc[i][7]-sa[i]-sb[7];
        *(float4*)row = v0;
        *(float4*)(row + 4) = v1;
    }
}

// ---------------- knn v3: 3-pass radix select (24 bits) + exact tiny-tail selection ----------------
// After 3 passes the boundary bin holds the only unresolved candidates (typically 1-3).
// Collect them (<=128) and exact-select by (key desc, idx asc) on one thread.
// Pathological many-ties fall back to a scan over the retained skeys.
__global__ __launch_bounds__(256) void knn_kernel() {
    int bn = blockIdx.x;
    int b = bn >> 10;
    __shared__ unsigned int skeys[NPTS];
    __shared__ int hist[256];
    __shared__ int wtot[8];
    __shared__ int s_bsel, s_above, s_cnt, s_ecnt;
    __shared__ unsigned int s_eqk[128];
    __shared__ int s_eqi[128];
    const float4* nd4 = (const float4*)(g_G + ((size_t)b << 20) + ((size_t)(bn & 1023) << 10));
    int t = threadIdx.x;
    int lane = t & 31, w = t >> 5;
    float4 d = nd4[t];
    unsigned int rkeys[4] = { fenc(d.x), fenc(d.y), fenc(d.z), fenc(d.w) };
    ((uint4*)skeys)[t] = make_uint4(rkeys[0], rkeys[1], rkeys[2], rkeys[3]);
    unsigned int prefix = 0, pmask = 0;
    int need = KNB;
    // ---- 3 radix passes: bits [31:24], [23:16], [15:8] ----
    for (int shift = 24; shift >= 8; shift -= 8) {
        hist[t] = 0;
        __syncthreads();
#pragma unroll
        for (int j = 0; j < 4; j++) {
            unsigned int k = rkeys[j];
            bool act = ((k & pmask) == prefix);
            int bin = act ? (int)((k >> shift) & 255) : (300 + j);
            unsigned int m = __match_any_sync(0xffffffffu, bin);
            if (act && ((m & ((1u << lane) - 1u)) == 0u))
                atomicAdd(&hist[bin], __popc(m));
        }
        __syncthreads();
        int c = hist[t];
        int s = c;
#pragma unroll
        for (int off = 1; off < 32; off <<= 1) {
            int o = __shfl_down_sync(0xffffffffu, s, off);
            if (lane + off < 32) s += o;
        }
        if (lane == 0) wtot[w] = s;
        __syncthreads();
        int offsum = 0;
        for (int w2 = w + 1; w2 < 8; w2++) offsum += wtot[w2];
        int sfx = s + offsum;
        int nxt = sfx - c;
        if (sfx >= need && nxt < need) { s_bsel = t; s_above = nxt; }
        __syncthreads();
        prefix |= ((unsigned int)s_bsel) << shift;
        pmask  |= 255u << shift;
        need   -= s_above;
        __syncthreads();
    }
    if (t == 0) { s_cnt = 0; s_ecnt = 0; }
    __syncthreads();
    int* out = g_idx + bn * KNB;
    // ---- collection on 24-bit prefix: strictly-greater -> out; boundary bin -> candidate list ----
#pragma unroll
    for (int j = 0; j < 4; j++) {
        unsigned int k = rkeys[j];
        unsigned int kp = k & pmask;
        int idx = 4 * t + j;
        bool gt = (kp > prefix);
        unsigned int bal = __ballot_sync(0xffffffffu, gt);
        if (bal) {
            int ldr = __ffs(bal) - 1;
            int base = 0;
            if (lane == ldr) base = atomicAdd(&s_cnt, __popc(bal));
            base = __shfl_sync(0xffffffffu, base, ldr);
            if (gt) out[base + __popc(bal & ((1u << lane) - 1u))] = idx;
        }
        bool eq = (kp == prefix);
        unsigned int be = __ballot_sync(0xffffffffu, eq);
        if (be) {
            int ldr = __ffs(be) - 1;
            int base = 0;
            if (lane == ldr) base = atomicAdd(&s_ecnt, __popc(be));
            base = __shfl_sync(0xffffffffu, base, ldr);
            if (eq) {
                int p = base + __popc(be & ((1u << lane) - 1u));
                if (p < 128) { s_eqk[p] = k; s_eqi[p] = idx; }
            }
        }
    }
    __syncthreads();
    // ---- exact tail: select 'need' from candidates by (key desc, idx asc) ----
    if (t == 0) {
        int p = s_cnt;           // == KNB - need
        int L = s_ecnt;
        if (L == need && L <= 128) {
            for (int i = 0; i < L; i++) out[p++] = s_eqi[i];
        } else if (L <= 128) {
            for (int r = 0; r < need; r++) {
                int bi = -1; unsigned int bk = 0u; int bidx = 0x7FFFFFFF;
                for (int i = 0; i < L; i++) {
                    int ii = s_eqi[i];
                    if (ii < 0) continue;
                    unsigned int kk = s_eqk[i];
                    if (bi < 0 || kk > bk || (kk == bk && ii < bidx)) { bi = i; bk = kk; bidx = ii; }
                }
                out[p++] = bidx;
                s_eqi[bi] = -1;
            }
        } else {
            // pathological: many ties in the 24-bit boundary bin; exact scan over skeys
            for (int r = 0; r < need; r++) {
                int bidx = -1; unsigned int bk = 0u;
                for (int i = 0; i < NPTS; i++) {
                    unsigned int kk = skeys[i];
                    if ((kk & pmask) != prefix) continue;
                    if (bidx < 0 || kk > bk) { bidx = i; bk = kk; }
                }
                out[p++] = bidx;
                skeys[bidx] = ~prefix;   // remove from candidate set
            }
        }
    }
}

// ---------------- uv2: W transposed in smem (proven) ----------------
template<int C, int COUT>
__global__ __launch_bounds__(256) void uv2_kernel(const float* __restrict__ x, int bstride,
                                                  const float* __restrict__ W) {
    extern __shared__ float sm[];
    float* sW = sm;                    // [2C][COUT]
    float* sx = sm + 2 * C * COUT;     // [16][C]
    int t = threadIdx.x;
    int bn0 = blockIdx.x * 16;
    int b = bn0 >> 10, n0 = bn0 & 1023;
    const float* xb = x + (size_t)b * bstride;
    for (int i = t; i < 2 * C * COUT; i += 256) {
        int o = i % COUT, c = i / COUT;
        sW[i] = W[(size_t)o * 2 * C + c];
    }
    for (int i = t; i < 16 * C; i += 256) {
        int r = i & 15, c = i >> 4;
        sx[r * C + c] = xb[(size_t)c * NPTS + n0 + r];
    }
    __syncthreads();
    for (int i = t; i < 16 * COUT; i += 256) {
        int nl = i / COUT, o = i % COUT;
        float u = 0.f, v = 0.f;
#pragma unroll
        for (int c = 0; c < C; c++) {
            float xv = sx[nl * C + c];
            float w1 = sW[c * COUT + o];
            float w2 = sW[(C + c) * COUT + o];
            u = fmaf(w1, xv, u);
            v = fmaf(w2 - w1, xv, v);
        }
        size_t bn = (size_t)(bn0 + nl);
        g_u[bn * COUT + o] = u;
        g_v[bn * COUT + o] = v;
    }
}

// =====================================================================================
// back_kernel (r15-proven, 24.6us measured incl. barrier; unroll 4)
// =====================================================================================
__global__ __launch_bounds__(256) void back_kernel(int Cout, int gsoff, unsigned int epoch,
                                                   const float* __restrict__ gnw,
                                                   const float* __restrict__ gnb,
                                                   float* __restrict__ feat, int choff) {
    __shared__ int sidx[16 * KNB];
    __shared__ double sacc[4];
    __shared__ double sg[4];
    int t = threadIdx.x, lane = t & 31;
    int TPP = Cout >> 2;
    int ppb = 256 / TPP;
    int passes = 16 / ppb;
    int bn0 = blockIdx.x * 16;
    int b = bn0 >> 10;
    int o4 = t % TPP;
    int pl0 = t / TPP;

    if (t < 4) sacc[t] = 0.0;
    for (int i = t; i < 16 * KNB; i += 256) sidx[i] = g_idx[bn0 * KNB + i];
    __syncthreads();

    const float4* ub = (const float4*)g_u + (size_t)(b << 10) * TPP;
    int half = TPP >> 1;
    int g = o4 / half;
    float4 rymx[2], rymn[2];
    const float Kf = (float)KNB;

    for (int p = 0; p < passes; p++) {
        int pl = p * ppb + pl0;
        int bn = bn0 + pl;
        const int* myidx = sidx + pl * KNB;
        float4 mx = make_float4(-CUDART_INF_F, -CUDART_INF_F, -CUDART_INF_F, -CUDART_INF_F);
        float4 mn = make_float4(CUDART_INF_F, CUDART_INF_F, CUDART_INF_F, CUDART_INF_F);
        float4 s1 = make_float4(0, 0, 0, 0), s2 = make_float4(0, 0, 0, 0);
        for (int k = 0; k < KNB; k += 4) {
            float4 v0 = ub[(size_t)myidx[k] * TPP + o4];
            float4 v1 = ub[(size_t)myidx[k + 1] * TPP + o4];
            float4 v2 = ub[(size_t)myidx[k + 2] * TPP + o4];
            float4 v3 = ub[(size_t)myidx[k + 3] * TPP + o4];
#define ACC(vv) \
            mx.x = fmaxf(mx.x, vv.x); mn.x = fminf(mn.x, vv.x); s1.x += vv.x; s2.x = fmaf(vv.x, vv.x, s2.x); \
            mx.y = fmaxf(mx.y, vv.y); mn.y = fminf(mn.y, vv.y); s1.y += vv.y; s2.y = fmaf(vv.y, vv.y, s2.y); \
            mx.z = fmaxf(mx.z, vv.z); mn.z = fminf(mn.z, vv.z); s1.z += vv.z; s2.z = fmaf(vv.z, vv.z, s2.z); \
            mx.w = fmaxf(mx.w, vv.w); mn.w = fminf(mn.w, vv.w); s1.w += vv.w; s2.w = fmaf(vv.w, vv.w, s2.w);
            ACC(v0) ACC(v1) ACC(v2) ACC(v3)
#undef ACC
        }
        float4 v = ((const float4*)g_v)[(size_t)bn * TPP + o4];
        rymx[p] = make_float4(mx.x + v.x, mx.y + v.y, mx.z + v.z, mx.w + v.w);
        rymn[p] = make_float4(mn.x + v.x, mn.y + v.y, mn.z + v.z, mn.w + v.w);
        float S1 = (s1.x + Kf * v.x) + (s1.y + Kf * v.y) + (s1.z + Kf * v.z) + (s1.w + Kf * v.w);
        float S2 = (s2.x + 2.f * v.x * s1.x + Kf * v.x * v.x)
                 + (s2.y + 2.f * v.y * s1.y + Kf * v.y * v.y)
                 + (s2.z + 2.f * v.z * s1.z + Kf * v.z * v.z)
                 + (s2.w + 2.f * v.w * s1.w + Kf * v.w * v.w);
#pragma unroll
        for (int off = 8; off > 0; off >>= 1) {
            if (off < half) {
                S1 += __shfl_down_sync(0xffffffffu, S1, off, half);
                S2 += __shfl_down_sync(0xffffffffu, S2, off, half);
            }
        }
        if ((lane & (half - 1)) == 0) {
            int gg = (lane / half) & 1;
            atomicAdd(&sacc[gg * 2 + 0], (double)S1);
            atomicAdd(&sacc[gg * 2 + 1], (double)S2);
        }
    }
    __syncthreads();
    if (t < 4) atomicAdd(&g_gs[gsoff + (b * 2 + (t >> 1)) * 2 + (t & 1)], sacc[t]);

    grid_barrier(epoch, 256u);

    if (t < 4) sg[t] = __ldcg(&g_gs[gsoff + (b * 2 + (t >> 1)) * 2 + (t & 1)]);
    __syncthreads();

    double cntr = (double)(Cout >> 1) * (double)NPTS * (double)KNB;
    double S1g = sg[g * 2 + 0];
    double S2g = sg[g * 2 + 1];
    double mud = S1g / cntr;
    float var = (float)(S2g / cntr - mud * mud);
    float rsq = rsqrtf(var + 1e-5f);
    float mu = (float)mud;
    float A[4], Bb[4];
#pragma unroll
    for (int j = 0; j < 4; j++) {
        int o = 4 * o4 + j;
        A[j] = gnw[o] * rsq;
        Bb[j] = gnb[o] - mu * A[j];
    }
    for (int p = 0; p < passes; p++) {
        int pl = p * ppb + pl0;
        int n = (bn0 & 1023) + pl;
        float* fb = feat + (size_t)b * 262144 + (size_t)choff * NPTS + n;
        float mxv[4] = { rymx[p].x, rymx[p].y, rymx[p].z, rymx[p].w };
        float mnv[4] = { rymn[p].x, rymn[p].y, rymn[p].z, rymn[p].w };
#pragma unroll
        for (int j = 0; j < 4; j++) {
            float c1 = fmaf(A[j], mxv[j], Bb[j]);
            float c2 = fmaf(A[j], mnv[j], Bb[j]);
            c1 = c1 >= 0.f ? c1 : 0.2f * c1;
            c2 = c2 >= 0.f ? c2 : 0.2f * c2;
            fb[(size_t)(4 * o4 + j) * NPTS] = fmaxf(c1, c2);
        }
    }
}

// =====================================================================================
// tail_kernel (proven): final matmul + stats + grid barrier + GN/relu/max output
// =====================================================================================
__global__ __launch_bounds__(256, 2) void tail_kernel(const float* __restrict__ feat,
                                                      const float* __restrict__ W,
                                                      const float* __restrict__ bias,
                                                      const float* __restrict__ gnw,
                                                      const float* __restrict__ gnb,
                                                      float* __restrict__ out) {
    int b = blockIdx.z;
    int co0 = blockIdx.x * 128, n0 = blockIdx.y * 128;
    __shared__ float Ws[32][132];
    __shared__ float Xs[32][128];
    int t = threadIdx.x, tx = t & 15, ty = t >> 4;
    int lane = t & 31, w = t >> 5;
    float acc[8][8] = {};
    const float* fb = feat + (size_t)b * 262144;
#pragma unroll
    for (int cc = 0; cc < 256; cc += 32) {
        __syncthreads();
#pragma unroll 4
        for (int i = t; i < 32 * 128; i += 256) {
            int row = i >> 5, c = i & 31;
            Ws[c][row] = W[(size_t)(co0 + row) * 256 + cc + c];
        }
#pragma unroll 4
        for (int i = t; i < 32 * 128; i += 256) {
            int nl = i & 127, c = i >> 7;
            Xs[c][nl] = fb[(size_t)(cc + c) * NPTS + n0 + nl];
        }
        __syncthreads();
#pragma unroll
        for (int c = 0; c < 32; c++) {
            float wv[8], xv[8];
            const float4* w4 = (const float4*)&Ws[c][ty * 8];
            const float4* x4 = (const float4*)&Xs[c][tx * 8];
            float4 p0 = w4[0], p1 = w4[1], q0 = x4[0], q1 = x4[1];
            wv[0]=p0.x;wv[1]=p0.y;wv[2]=p0.z;wv[3]=p0.w;wv[4]=p1.x;wv[5]=p1.y;wv[6]=p1.z;wv[7]=p1.w;
            xv[0]=q0.x;xv[1]=q0.y;xv[2]=q0.z;xv[3]=q0.w;xv[4]=q1.x;xv[5]=q1.y;xv[6]=q1.z;xv[7]=q1.w;
#pragma unroll
            for (int i = 0; i < 8; i++)
#pragma unroll
                for (int j = 0; j < 8; j++) acc[i][j] = fmaf(wv[i], xv[j], acc[i][j]);
        }
    }
    float s1t = 0.f, s2t = 0.f;
#pragma unroll
    for (int i = 0; i < 8; i++) {
        int co = co0 + ty * 8 + i;
        float bv = bias[co];
        float mx = -CUDART_INF_F, mn = CUDART_INF_F;
#pragma unroll
        for (int j = 0; j < 8; j++) {
            float y = acc[i][j] + bv;
            mx = fmaxf(mx, y); mn = fminf(mn, y);
            s1t += y; s2t = fmaf(y, y, s2t);
        }
#pragma unroll
        for (int off = 8; off > 0; off >>= 1) {
            mx = fmaxf(mx, __shfl_down_sync(0xffffffffu, mx, off, 16));
            mn = fminf(mn, __shfl_down_sync(0xffffffffu, mn, off, 16));
        }
        if (tx == 0) {
            atomicMax(&g_ymax[b * 1024 + co], fenc(mx));
            atomicMin(&g_ymin[b * 1024 + co], fenc(mn));
        }
    }
#pragma unroll
    for (int off = 16; off > 0; off >>= 1) {
        s1t += __shfl_down_sync(0xffffffffu, s1t, off);
        s2t += __shfl_down_sync(0xffffffffu, s2t, off);
    }
    __shared__ double sred[8][2];
    if (lane == 0) { sred[w][0] = (double)s1t; sred[w][1] = (double)s2t; }
    __syncthreads();
    if (t == 0) {
        double a = 0.0, c = 0.0;
        for (int i = 0; i < 8; i++) { a += sred[i][0]; c += sred[i][1]; }
        atomicAdd(&g_gs5[(b * 8 + blockIdx.x) * 2 + 0], a);
        atomicAdd(&g_gs5[(b * 8 + blockIdx.x) * 2 + 1], c);
    }

    grid_barrier(4u, 256u);

    if (t < 16) {
        int bid = blockIdx.x + (blockIdx.y << 3) + ((int)blockIdx.z << 6);
        int i = bid * 16 + t;
        int ob = i >> 10, c = i & 1023;
        int g = c >> 7;
        double cntr = 128.0 * 1024.0;
        double S1 = __ldcg(&g_gs5[(ob * 8 + g) * 2 + 0]);
        double S2 = __ldcg(&g_gs5[(ob * 8 + g) * 2 + 1]);
        double mud = S1 / cntr;
        float var = (float)(S2 / cntr - mud * mud);
        float rsq = rsqrtf(var + 1e-5f);
        float a = gnw[c] * rsq;
        float bb = gnb[c] - (float)mud * a;
        float ymx = fdec(__ldcg(&g_ymax[i]));
        float ymn = fdec(__ldcg(&g_ymin[i]));
        float c1 = fmaxf(fmaf(a, ymx, bb), 0.f);
        float c2 = fmaxf(fmaf(a, ymn, bb), 0.f);
        out[i] = fmaxf(c1, c2);
    }
}

// ---------------- launch ----------------
extern "C" void kernel_launch(void* const* d_in, const int* in_sizes, int n_in,
                              void* d_out, int out_size) {
    const float* x    = (const float*)d_in[0];
    const float* c1w  = (const float*)d_in[1];
    const float* g1w  = (const float*)d_in[2];
    const float* g1b  = (const float*)d_in[3];
    const float* c2w  = (const float*)d_in[4];
    const float* g2w  = (const float*)d_in[5];
    const float* g2b  = (const float*)d_in[6];
    const float* c3w  = (const float*)d_in[7];
    const float* g3w  = (const float*)d_in[8];
    const float* g3b  = (const float*)d_in[9];
    const float* mlpw = (const float*)d_in[10];
    const float* mlpb = (const float*)d_in[11];
    const float* g5w  = (const float*)d_in[12];
    const float* g5b  = (const float*)d_in[13];

    float* out  = (float*)d_out;
    float* feat = out + B * 1024;  // x_features region (B,256,N)

    const int SM_UV3_64   = (2 * 3 * 64 + 16 * 3) * 4;
    const int SM_UV64_64  = (2 * 64 * 64 + 16 * 64) * 4;
    const int SM_UV64_128 = (2 * 64 * 128 + 16 * 64) * 4;
    cudaFuncSetAttribute(uv2_kernel<64, 128>, cudaFuncAttributeMaxDynamicSharedMemorySize, SM_UV64_128);
    cudaFuncSetAttribute(uv2_kernel<64, 64>,  cudaFuncAttributeMaxDynamicSharedMemorySize, SM_UV64_64);

    zero_all_kernel<<<16, 256>>>();                                        // 1
    // layer 1
    uv2_kernel<3, 64><<<256, 256, SM_UV3_64>>>(x, 3 * NPTS, c1w);          // 2
    gram_kernel<3><<<dim3(8, 8, B), 256>>>(x, 3 * NPTS);                   // 3
    knn_kernel<<<B * NPTS, 256>>>();                                       // 4 (profiled slot)
    back_kernel<<<256, 256>>>(64, 0, 1u, g1w, g1b, feat, 0);               // 5

    // layer 2
    gram_kernel<64><<<dim3(8, 8, B), 256>>>(feat, 256 * NPTS);             // 6
    knn_kernel<<<B * NPTS, 256>>>();                                       // 7
    uv2_kernel<64, 64><<<256, 256, SM_UV64_64>>>(feat, 256 * NPTS, c2w);   // 8
    back_kernel<<<256, 256>>>(64, 16, 2u, g2w, g2b, feat, 64);             // 9

    // layer 3
    gram_kernel<64><<<dim3(8, 8, B), 256>>>(feat + 64 * NPTS, 256 * NPTS); // 10
    knn_kernel<<<B * NPTS, 256>>>();                                       // 11
    uv2_kernel<64, 128><<<256, 256, SM_UV64_128>>>(feat + 64 * NPTS, 256 * NPTS, c3w); // 12
    back_kernel<<<256, 256>>>(128, 32, 3u, g3w, g3b, feat, 128);           // 13

    tail_kernel<<<dim3(8, 8, B), 256>>>(feat, mlpw, mlpb, g5w, g5b, out);  // 14
}